// round 9
// baseline (speedup 1.0000x reference)
#include <cuda_runtime.h>
#include <cuda_fp16.h>
#include <cstdint>

typedef unsigned long long u64;

#define NQ 16384
#define NB 128
#define NF 64
#define HD 128
#define EPSF 1e-8f

#define THREADS 768
#define WARPS_PER_CTA 24
#define PAIRS_PER_CTA 12
#define MAXQ 5

// Half-packed probe table (prep output), 16B per (f,p) entry:
// halves: [Pr_p, Pr_p64, Pi_p, Pi_p64, w_p, w_p64, mw_p, mw_p64]
__device__ __half g_probeH[NF * 64 * 8];

// ---------- helpers ----------
__device__ __forceinline__ u64 f2pk(float lo, float hi) {
    u64 r; asm("mov.b64 %0, {%1,%2};" : "=l"(r) : "f"(lo), "f"(hi)); return r;
}
__device__ __forceinline__ void f2upk(float& lo, float& hi, u64 v) {
    asm("mov.b64 {%0,%1}, %2;" : "=f"(lo), "=f"(hi) : "l"(v));
}
__device__ __forceinline__ u64 f2fma(u64 a, u64 b, u64 c) {
    u64 d; asm("fma.rn.f32x2 %0, %1, %2, %3;" : "=l"(d) : "l"(a), "l"(b), "l"(c)); return d;
}
__device__ __forceinline__ float sqrt_apx(float x) {
    float r; asm("sqrt.approx.f32 %0, %1;" : "=f"(r) : "f"(x)); return r;
}
__device__ __forceinline__ float rcp_apx(float x) {
    float r; asm("rcp.approx.f32 %0, %1;" : "=f"(r) : "f"(x)); return r;
}
__device__ __forceinline__ uint32_t su32(const void* p) {
    uint32_t a;
    asm("{ .reg .u64 t; cvta.to.shared.u64 t, %1; cvt.u32.u64 %0, t; }"
        : "=r"(a) : "l"(p));
    return a;
}
__device__ __forceinline__ __half2 h2bits(uint32_t u) {
    __half2 h; *reinterpret_cast<uint32_t*>(&h) = u; return h;
}
__device__ __forceinline__ uint32_t bitsh2(__half2 h) {
    return *reinterpret_cast<uint32_t*>(&h);
}

// ---------- prep: one block per probe b, one thread per f ----------
__global__ __launch_bounds__(64)
void prep_kernel(const float* __restrict__ probes,
                 const float* __restrict__ angles,
                 const float* __restrict__ qw,
                 const float* __restrict__ qmw) {
    __shared__ float red[2];
    const int b = blockIdx.x;   // 0..127
    const int f = threadIdx.x;  // 0..63
    const int warp = f >> 5;
    const int lane = f & 31;

    float x0 = probes[b * HD + f];
    float x1 = probes[b * HD + NF + f];
    float ss = fmaf(x0, x0, x1 * x1);
#pragma unroll
    for (int o = 16; o; o >>= 1) ss += __shfl_xor_sync(0xffffffffu, ss, o);
    if (lane == 0) red[warp] = ss;
    __syncthreads();
    float inv = 1.0f / (sqrtf(red[0] + red[1]) + EPSF);

    float pr = x0 * inv;
    float pi = x1 * inv;
    float c, s;
    sincosf(angles[f], &s, &c);
    float Pr = pr * c - pi * s;
    float Pi = pr * s + pi * c;
    float xw = qw[b * NF + f];
    float sp = (xw > 20.0f) ? xw : log1pf(expf(xw));
    float w = -sp;
    float mw = qmw[b * NF + f];

    int p = b & 63;
    int hi = b >> 6;
    int base = (f * 64 + p) * 8;
    g_probeH[base + 0 + hi] = __float2half_rn(Pr);
    g_probeH[base + 2 + hi] = __float2half_rn(Pi);
    g_probeH[base + 4 + hi] = __float2half_rn(w);
    g_probeH[base + 6 + hi] = __float2half_rn(mw);
}

// ---------- SMEM layout (float offsets) ----------
#define OFF_SH  0        // probe half table: 4096 entries * 16B = 16384 floats (64KB)
#define OFF_QT  16384    // q-tables: 12 pairs * 5q * 64f * 16B = 15360 floats (60KB)
                         //   entry: {bits(-qr h2dup), bits(-qi h2dup), qm, qm}
#define OFF_QN  31744    // per-warp qn scratch: 24*128 = 3072 floats (12KB)
#define SMEM_FLOATS 34816 // 139264 bytes (136KB)

// f-loop over a batch of JN q's. Lane handles b-pair (p, p+64); half2/f32x2
// lanes are the b-pair. d2 math in HFMA2 (true dual-rate), acc in f32x2.
template<int JN>
__device__ __forceinline__ void run_batch(uint32_t aP, uint32_t aQT,
                                          u64 biasp,
                                          float* __restrict__ out, int q0, int p) {
    u64 acc[JN];
#pragma unroll
    for (int j = 0; j < JN; j++) acc[j] = biasp;

#pragma unroll 2
    for (int f = 0; f < NF; f++) {
        const uint32_t fo = (uint32_t)f * 1024u;
        u64 vlo, vhi;
        asm("ld.shared.v2.b64 {%0,%1}, [%2];" : "=l"(vlo), "=l"(vhi) : "r"(aP + fo));
        uint32_t uPr, uPi, uw, umw;
        asm("mov.b64 {%0,%1}, %2;" : "=r"(uPr), "=r"(uPi) : "l"(vlo));
        asm("mov.b64 {%0,%1}, %2;" : "=r"(uw),  "=r"(umw) : "l"(vhi));
        const __half2 Pr2 = h2bits(uPr);
        const __half2 Pi2 = h2bits(uPi);
        const float2 wf  = __half22float2(h2bits(uw));
        const float2 mwf = __half22float2(h2bits(umw));
        const u64 w2  = f2pk(wf.x, wf.y);
        const u64 mw2 = f2pk(mwf.x, mwf.y);

#pragma unroll
        for (int j = 0; j < JN; j++) {
            // broadcast load: {-qr h2dup, -qi h2dup} + {qm, qm} f32x2
            u64 va, qm2;
            asm("ld.shared.v2.b64 {%0,%1}, [%2];"
                : "=l"(va), "=l"(qm2)
                : "r"(aQT + ((uint32_t)j * 64u + (uint32_t)f) * 16u));
            uint32_t uqr, uqi;
            asm("mov.b64 {%0,%1}, %2;" : "=r"(uqr), "=r"(uqi) : "l"(va));

            __half2 er = __hadd2(Pr2, h2bits(uqr));   // P - Q (q pre-negated)
            __half2 ei = __hadd2(Pi2, h2bits(uqi));
            __half2 d2 = __hfma2(er, er, __hmul2(ei, ei));
            float2 d2f = __half22float2(d2);
            u64 dist = f2pk(sqrt_apx(d2f.x), sqrt_apx(d2f.y));
            acc[j] = f2fma(dist, w2, acc[j]);
            acc[j] = f2fma(qm2, mw2, acc[j]);
        }
    }

#pragma unroll
    for (int j = 0; j < JN; j++) {
        float o0, o1; f2upk(o0, o1, acc[j]);
        float* orow = out + (size_t)(q0 + j) * NB;
        orow[p]      = o0;
        orow[p + 64] = o1;
    }
}

__global__ __launch_bounds__(THREADS, 1)
void main_kernel(const float* __restrict__ Q,
                 const float* __restrict__ bias,
                 float* __restrict__ out) {
    extern __shared__ float sm[];
    const int tid  = threadIdx.x;
    const int warp = tid >> 5;
    const int lane = tid & 31;
    const int pid  = warp >> 1;     // pair id 0..11
    const int h    = warp & 1;      // warp half within pair
    const int p    = lane + 32 * h; // b-pair index 0..63

    // Stage half probe table into SMEM (64KB = 4096 float4)
    {
        const float4* gH = (const float4*)g_probeH;
        float4* sH4 = (float4*)(sm + OFF_SH);
        for (int i = tid; i < NF * 64; i += THREADS)
            sH4[i] = gH[i];
    }

    const u64 biasp = f2pk(bias[p], bias[p + 64]);

    __syncthreads();

    const uint32_t sbase = su32(sm);
    const uint32_t aP  = sbase + (uint32_t)p * 16u;
    const uint32_t aQT = sbase + ((uint32_t)OFF_QT * 4u) + (uint32_t)pid * (MAXQ * 64u * 16u);
    float*  qn = sm + OFF_QN + warp * 128;
    float4* qt = (float4*)(sm + OFF_QT + pid * MAXQ * 64 * 4);

    // ---- contiguous q-range per warp-pair (balanced to +/-1 q) ----
    const int npairs = gridDim.x * PAIRS_PER_CTA;
    const int gp = blockIdx.x * PAIRS_PER_CTA + pid;
    const int per = NQ / npairs;
    const int rem = NQ % npairs;
    int cnt, q0;
    if (gp < rem) { cnt = per + 1; q0 = gp * (per + 1); }
    else          { cnt = per;     q0 = rem * (per + 1) + (gp - rem) * per; }

    while (cnt > 0) {
        const int jn = (cnt > MAXQ) ? 4 : cnt;   // 9 -> 4+5, 8 -> 4+4

        // ---- batch prep: warps of the pair split q's by parity ----
        for (int j = h; j < jn; j += 2) {
            const float4* Qv = (const float4*)(Q + (size_t)(q0 + j) * HD);
            float4 v = Qv[lane];
            float ss = fmaf(v.x, v.x, fmaf(v.y, v.y, fmaf(v.z, v.z, v.w * v.w)));
#pragma unroll
            for (int o = 16; o; o >>= 1) ss += __shfl_xor_sync(0xffffffffu, ss, o);
            float inv = rcp_apx(sqrt_apx(ss) + EPSF);
            ((float4*)qn)[lane] = make_float4(v.x * inv, v.y * inv, v.z * inv, v.w * inv);
            __syncwarp();
#pragma unroll
            for (int k = 0; k < 2; k++) {
                int f = lane + k * 32;
                float qr = qn[f];
                float qi = qn[f + 64];
                float qm = sqrt_apx(fmaf(qr, qr, fmaf(qi, qi, EPSF)));
                uint32_t uqr = bitsh2(__floats2half2_rn(-qr, -qr));
                uint32_t uqi = bitsh2(__floats2half2_rn(-qi, -qi));
                qt[j * 64 + f] = make_float4(__uint_as_float(uqr),
                                             __uint_as_float(uqi), qm, qm);
            }
            __syncwarp();
        }
        // pair-scoped named barrier (ids 1..12)
        asm volatile("bar.sync %0, %1;" :: "r"(pid + 1), "r"(64) : "memory");

        switch (jn) {
            case 5:  run_batch<5>(aP, aQT, biasp, out, q0, p); break;
            case 4:  run_batch<4>(aP, aQT, biasp, out, q0, p); break;
            case 3:  run_batch<3>(aP, aQT, biasp, out, q0, p); break;
            case 2:  run_batch<2>(aP, aQT, biasp, out, q0, p); break;
            default: run_batch<1>(aP, aQT, biasp, out, q0, p); break;
        }

        // protect q-tables against next batch's overwrite
        asm volatile("bar.sync %0, %1;" :: "r"(pid + 1), "r"(64) : "memory");

        q0 += jn;
        cnt -= jn;
    }
}

extern "C" void kernel_launch(void* const* d_in, const int* in_sizes, int n_in,
                              void* d_out, int out_size) {
    const float* Q      = (const float*)d_in[0];
    const float* angles = (const float*)d_in[1];
    const float* probes = (const float*)d_in[2];
    const float* qw     = (const float*)d_in[3];
    const float* qmw    = (const float*)d_in[4];
    const float* qbias  = (const float*)d_in[5];
    float* out = (float*)d_out;

    // probe table: NF*64 entries * 16B = 4 floats each
    static_assert(OFF_QT == OFF_SH + NF * 64 * 4, "probe region");
    static_assert(OFF_QN == OFF_QT + PAIRS_PER_CTA * MAXQ * 64 * 4, "qt region");
    static_assert(SMEM_FLOATS == OFF_QN + WARPS_PER_CTA * 128, "qn region");
    static_assert(SMEM_FLOATS * sizeof(float) <= 232448, "smem cap");

    cudaFuncSetAttribute(main_kernel,
                         cudaFuncAttributeMaxDynamicSharedMemorySize,
                         SMEM_FLOATS * (int)sizeof(float));

    int sms = 148;
    cudaDeviceGetAttribute(&sms, cudaDevAttrMultiProcessorCount, 0);

    prep_kernel<<<NB, 64>>>(probes, angles, qw, qmw);
    main_kernel<<<sms, THREADS, SMEM_FLOATS * sizeof(float)>>>(Q, qbias, out);
}